// round 11
// baseline (speedup 1.0000x reference)
#include <cuda_runtime.h>
#include <cuda_bf16.h>
#include <cstdint>

#define BATCH   65536
#define SLEN    128
#define NCLS    10
#define SD      14
#define D       256
#define TM      128     // tasks per block (GEMM M)
#define THREADS 512

// w2^T bf16 hi/lo, pre-packed in mma.sync B-fragment order:
// uint32 index = ((kc*8 + wc)*32 + lane)*8 + j*2 + r
__device__ __align__(16) uint32_t g_w2fH[16 * 8 * 32 * 8];
__device__ __align__(16) uint32_t g_w2fL[16 * 8 * 32 * 8];

#define BSTRIDE_U4 512   // uint4 elements per kc step

__device__ __forceinline__ uint32_t s2u(const void* p) {
    return (uint32_t)__cvta_generic_to_shared(p);
}

__device__ __forceinline__ uint32_t pack_bf16(float a, float b) {
    __nv_bfloat162 t = __floats2bfloat162_rn(a, b);
    return *reinterpret_cast<uint32_t*>(&t);
}

__device__ __forceinline__ void ldsm4(uint32_t* r, uint32_t addr) {
    asm volatile("ldmatrix.sync.aligned.m8n8.x4.shared.b16 {%0,%1,%2,%3}, [%4];"
                 : "=r"(r[0]), "=r"(r[1]), "=r"(r[2]), "=r"(r[3]) : "r"(addr));
}

__device__ __forceinline__ void mma16816(float* c, const uint32_t* a, uint32_t b0, uint32_t b1) {
    asm volatile(
        "mma.sync.aligned.m16n8k16.row.col.f32.bf16.bf16.f32 "
        "{%0,%1,%2,%3}, {%4,%5,%6,%7}, {%8,%9}, {%0,%1,%2,%3};\n"
        : "+f"(c[0]), "+f"(c[1]), "+f"(c[2]), "+f"(c[3])
        : "r"(a[0]), "r"(a[1]), "r"(a[2]), "r"(a[3]), "r"(b0), "r"(b1));
}

// ---------------- prep: w2 -> bf16 hi/lo in fragment order ----------------
__global__ void prep_w2_kernel(const float* __restrict__ w2) {
    int idx = blockIdx.x * blockDim.x + threadIdx.x;   // 16384 threads
    if (idx >= 16 * 32 * 32) return;
    const int lane = idx & 31;
    const int nt   = (idx >> 5) & 31;     // global n-tile 0..31
    const int kc   = idx >> 10;           // 0..15
    const int n    = nt * 8 + (lane >> 2);
    const int k0   = kc * 16 + (lane & 3) * 2;
    const int wc   = nt >> 2;
    const int j    = nt & 3;
    const uint32_t pos = (uint32_t)(((kc * 8 + wc) * 32 + lane) * 8 + j * 2);

#pragma unroll
    for (int r = 0; r < 2; ++r) {
        const int k = k0 + r * 8;
        float v0 = w2[(size_t)k * D + n];
        float v1 = w2[(size_t)(k + 1) * D + n];
        __nv_bfloat16 h0 = __float2bfloat16(v0);
        __nv_bfloat16 h1 = __float2bfloat16(v1);
        g_w2fH[pos + r] = pack_bf16(__bfloat162float(h0), __bfloat162float(h1));
        g_w2fL[pos + r] = pack_bf16(v0 - __bfloat162float(h0), v1 - __bfloat162float(h1));
    }
}

// ---------------- main fused kernel ----------------
#define APITCH 264   // bf16 elements per row (256 + 8 pad) -> 528 bytes

struct Smem {
    __align__(16) __nv_bfloat16 Ah[TM][APITCH];   // 66 KB
    __align__(16) __nv_bfloat16 Al[TM][APITCH];   // 66 KB
    float w1[SD][D];                              // 14 KB
    float stats[TM][16];                          // 8 KB
    float b1[D];
    float b2[D];
};

__global__ void __launch_bounds__(THREADS, 1)
tte_mma_kernel(const int* __restrict__ y,
               const float* __restrict__ g_w1,
               const float* __restrict__ g_b1,
               const float* __restrict__ g_b2,
               float* __restrict__ out)
{
    extern __shared__ char smem_raw[];
    Smem& sm = *reinterpret_cast<Smem*>(smem_raw);

    const int tid  = threadIdx.x;
    const int lane = tid & 31;
    const int wid  = tid >> 5;          // 0..15
    const int task0 = blockIdx.x * TM;

    // ---- load w1/b1/b2 ----
    {
        float* w1f = &sm.w1[0][0];
        for (int i = tid; i < SD * D; i += THREADS) w1f[i] = g_w1[i];
        if (tid < D) { sm.b1[tid] = g_b1[tid]; sm.b2[tid] = g_b2[tid]; }
    }

    // ---- Phase 1: per-task histogram stats (warp per task, 8 tasks/warp) ----
#pragma unroll
    for (int it = 0; it < TM / 16; ++it) {
        const int tt = wid * (TM / 16) + it;
        const int4 yv = *reinterpret_cast<const int4*>(
            y + (size_t)(task0 + tt) * SLEN + lane * 4);
        int cnt[NCLS];
#pragma unroll
        for (int c = 0; c < NCLS; ++c) {
            int m = (yv.x == c) + (yv.y == c) + (yv.z == c) + (yv.w == c);
            cnt[c] = __reduce_add_sync(0xffffffffu, m);
        }
        if (lane == 0) {
            float ent = 0.0f, pmax = 0.0f;
            int   nnz = 0;
#pragma unroll
            for (int c = 0; c < NCLS; ++c) {
                float pc = (float)cnt[c] * (1.0f / (float)SLEN);
                sm.stats[tt][c] = pc;
                ent  -= pc * logf(pc + 1e-6f);
                nnz  += (cnt[c] > 0);
                pmax  = fmaxf(pmax, pc);
            }
            sm.stats[tt][10] = (float)nnz;
            sm.stats[tt][11] = ent;
            sm.stats[tt][12] = (float)SLEN;
            sm.stats[tt][13] = pmax;
        }
    }
    __syncthreads();

    // ---- Phase 2: h = gelu(stats @ w1 + b1) -> bf16 hi/lo smem images ----
    // 16 warps: warp owns rows [wid*8, wid*8+8), lane owns cols [lane*8, lane*8+8)
    {
        const int ty = wid;
        const int tx = lane;
        float acc[8][8];
#pragma unroll
        for (int i = 0; i < 8; ++i)
#pragma unroll
            for (int j = 0; j < 8; ++j) acc[i][j] = sm.b1[tx * 8 + j];
#pragma unroll
        for (int k = 0; k < SD; ++k) {
            float a[8], b[8];
#pragma unroll
            for (int i = 0; i < 8; ++i) a[i] = sm.stats[ty * 8 + i][k];
#pragma unroll
            for (int j = 0; j < 8; ++j) b[j] = sm.w1[k][tx * 8 + j];
#pragma unroll
            for (int i = 0; i < 8; ++i)
#pragma unroll
                for (int j = 0; j < 8; ++j) acc[i][j] = fmaf(a[i], b[j], acc[i][j]);
        }
#pragma unroll
        for (int i = 0; i < 8; ++i) {
            const int m = ty * 8 + i;
            uint32_t hi[4], lo[4];
#pragma unroll
            for (int q = 0; q < 4; ++q) {
                float x0 = acc[i][2 * q], x1 = acc[i][2 * q + 1];
                float g0 = 0.5f * x0 * (1.0f + erff(x0 * 0.70710678118654752f));
                float g1 = 0.5f * x1 * (1.0f + erff(x1 * 0.70710678118654752f));
                __nv_bfloat16 h0 = __float2bfloat16(g0);
                __nv_bfloat16 h1 = __float2bfloat16(g1);
                hi[q] = pack_bf16(__bfloat162float(h0), __bfloat162float(h1));
                lo[q] = pack_bf16(g0 - __bfloat162float(h0), g1 - __bfloat162float(h1));
            }
            *reinterpret_cast<uint4*>(&sm.Ah[m][tx * 8]) = make_uint4(hi[0], hi[1], hi[2], hi[3]);
            *reinterpret_cast<uint4*>(&sm.Al[m][tx * 8]) = make_uint4(lo[0], lo[1], lo[2], lo[3]);
        }
    }
    __syncthreads();

    // ---- Phase 3: out = h @ w2 + b2, interleaved 3-term, mt-major inner loop ----
    // 16 warps: hw = wid>>3 -> rows [hw*64, hw*64+64); cg = wid&7 -> cols [cg*32, cg*32+32)
    const int hw = wid >> 3;
    const int cg = wid & 7;

    // verified lane->address map: a-regs [r0-7,k0-7],[r8-15,k0-7],[r0-7,k8-15],[r8-15,k8-15]
    const int arow_l = (lane & 7) + ((lane >> 3) & 1) * 8;
    const int kofs_l = (lane >> 4) * 16;

    float acc[4][4][4];
#pragma unroll
    for (int mt = 0; mt < 4; ++mt)
#pragma unroll
        for (int nt = 0; nt < 4; ++nt)
#pragma unroll
            for (int q = 0; q < 4; ++q) acc[mt][nt][q] = 0.0f;

    const uint32_t mstride = 16u * (APITCH * 2);
    uint32_t adrH = s2u(&sm.Ah[0][0]) + (uint32_t)((hw * 64 + arow_l) * (APITCH * 2) + kofs_l);
    uint32_t adrL = s2u(&sm.Al[0][0]) + (uint32_t)((hw * 64 + arow_l) * (APITCH * 2) + kofs_l);

    const uint4* __restrict__ bptrH = reinterpret_cast<const uint4*>(g_w2fH) + (cg * 32 + lane) * 2;
    const uint4* __restrict__ bptrL = reinterpret_cast<const uint4*>(g_w2fL) + (cg * 32 + lane) * 2;

    // prefetch kc=0
    uint4 pH0 = bptrH[0], pH1 = bptrH[1];
    uint4 pL0 = bptrL[0], pL1 = bptrL[1];
    bptrH += BSTRIDE_U4; bptrL += BSTRIDE_U4;

#pragma unroll
    for (int kc = 0; kc < 16; ++kc) {
        const uint4 h0 = pH0, h1 = pH1, l0 = pL0, l1 = pL1;
        if (kc < 15) {
            pH0 = bptrH[0]; pH1 = bptrH[1];
            pL0 = bptrL[0]; pL1 = bptrL[1];
            bptrH += BSTRIDE_U4; bptrL += BSTRIDE_U4;
        }

        const uint32_t bh[4][2] = { {h0.x, h0.y}, {h0.z, h0.w}, {h1.x, h1.y}, {h1.z, h1.w} };
        const uint32_t bl[4][2] = { {l0.x, l0.y}, {l0.z, l0.w}, {l1.x, l1.y}, {l1.z, l1.w} };

        // mt-major: only one mt's A fragments (8 regs) live at a time
#pragma unroll
        for (int mt = 0; mt < 4; ++mt) {
            uint32_t ah[4], al[4];
            ldsm4(ah, adrH + mt * mstride);
            ldsm4(al, adrL + mt * mstride);
#pragma unroll
            for (int nt = 0; nt < 4; ++nt) {
                mma16816(acc[mt][nt], ah, bh[nt][0], bh[nt][1]);
                mma16816(acc[mt][nt], ah, bl[nt][0], bl[nt][1]);
                mma16816(acc[mt][nt], al, bh[nt][0], bh[nt][1]);
            }
        }
        adrH += 32;
        adrL += 32;
    }

    // ---- Epilogue: + b2, streaming store ----
    const int colb = cg * 32;
    const int r_in = lane >> 2;
    const int c_in = (lane & 3) * 2;
#pragma unroll
    for (int nt = 0; nt < 4; ++nt) {
        const int col = colb + nt * 8 + c_in;
        const float bb0 = sm.b2[col], bb1 = sm.b2[col + 1];
#pragma unroll
        for (int mt = 0; mt < 4; ++mt) {
            const size_t r0 = (size_t)(task0 + hw * 64 + mt * 16 + r_in);
            asm volatile("st.global.cs.v2.f32 [%0], {%1,%2};"
                         :: "l"(out + r0 * D + col),
                            "f"(acc[mt][nt][0] + bb0), "f"(acc[mt][nt][1] + bb1) : "memory");
            asm volatile("st.global.cs.v2.f32 [%0], {%1,%2};"
                         :: "l"(out + (r0 + 8) * D + col),
                            "f"(acc[mt][nt][2] + bb0), "f"(acc[mt][nt][3] + bb1) : "memory");
        }
    }
}

extern "C" void kernel_launch(void* const* d_in, const int* in_sizes, int n_in,
                              void* d_out, int out_size)
{
    (void)in_sizes; (void)n_in; (void)out_size;
    const int*   y  = (const int*)  d_in[0];
    const float* w1 = (const float*)d_in[1];
    const float* b1 = (const float*)d_in[2];
    const float* w2 = (const float*)d_in[3];
    const float* b2 = (const float*)d_in[4];
    float* out = (float*)d_out;

    prep_w2_kernel<<<64, 256>>>(w2);

    const int smem = (int)sizeof(Smem);
    cudaFuncSetAttribute(tte_mma_kernel,
                         cudaFuncAttributeMaxDynamicSharedMemorySize, smem);
    tte_mma_kernel<<<BATCH / TM, THREADS, smem>>>(y, w1, b1, b2, out);
}

// round 12
// speedup vs baseline: 1.5595x; 1.5595x over previous
#include <cuda_runtime.h>
#include <cuda_bf16.h>
#include <cstdint>

#define BATCH   65536
#define SLEN    128
#define NCLS    10
#define SD      14
#define D       256
#define TM      128     // tasks per block (GEMM M)
#define THREADS 512

// w2^T bf16 hi/lo, pre-packed in mma.sync B-fragment order:
// uint32 index = ((kc*8 + wc)*32 + lane)*8 + j*2 + r
__device__ __align__(16) uint32_t g_w2fH[16 * 8 * 32 * 8];
__device__ __align__(16) uint32_t g_w2fL[16 * 8 * 32 * 8];

#define BSTRIDE_U4 512   // uint4 elements per kc step

__device__ __forceinline__ uint32_t s2u(const void* p) {
    return (uint32_t)__cvta_generic_to_shared(p);
}

__device__ __forceinline__ uint32_t pack_bf16(float a, float b) {
    __nv_bfloat162 t = __floats2bfloat162_rn(a, b);
    return *reinterpret_cast<uint32_t*>(&t);
}

__device__ __forceinline__ void ldsm4(uint32_t* r, uint32_t addr) {
    asm volatile("ldmatrix.sync.aligned.m8n8.x4.shared.b16 {%0,%1,%2,%3}, [%4];"
                 : "=r"(r[0]), "=r"(r[1]), "=r"(r[2]), "=r"(r[3]) : "r"(addr));
}

__device__ __forceinline__ void mma16816(float* c, const uint32_t* a, uint32_t b0, uint32_t b1) {
    asm volatile(
        "mma.sync.aligned.m16n8k16.row.col.f32.bf16.bf16.f32 "
        "{%0,%1,%2,%3}, {%4,%5,%6,%7}, {%8,%9}, {%0,%1,%2,%3};\n"
        : "+f"(c[0]), "+f"(c[1]), "+f"(c[2]), "+f"(c[3])
        : "r"(a[0]), "r"(a[1]), "r"(a[2]), "r"(a[3]), "r"(b0), "r"(b1));
}

// ---------------- prep: w2 -> bf16 hi/lo in fragment order ----------------
__global__ void prep_w2_kernel(const float* __restrict__ w2) {
    int idx = blockIdx.x * blockDim.x + threadIdx.x;   // 16384 threads
    if (idx >= 16 * 32 * 32) return;
    const int lane = idx & 31;
    const int nt   = (idx >> 5) & 31;     // global n-tile 0..31
    const int kc   = idx >> 10;           // 0..15
    const int n    = nt * 8 + (lane >> 2);
    const int k0   = kc * 16 + (lane & 3) * 2;
    const int wc   = nt >> 2;
    const int j    = nt & 3;
    const uint32_t pos = (uint32_t)(((kc * 8 + wc) * 32 + lane) * 8 + j * 2);

#pragma unroll
    for (int r = 0; r < 2; ++r) {
        const int k = k0 + r * 8;
        float v0 = w2[(size_t)k * D + n];
        float v1 = w2[(size_t)(k + 1) * D + n];
        __nv_bfloat16 h0 = __float2bfloat16(v0);
        __nv_bfloat16 h1 = __float2bfloat16(v1);
        g_w2fH[pos + r] = pack_bf16(__bfloat162float(h0), __bfloat162float(h1));
        g_w2fL[pos + r] = pack_bf16(v0 - __bfloat162float(h0), v1 - __bfloat162float(h1));
    }
}

// ---------------- main fused kernel ----------------
#define APITCH 264   // bf16 elements per row (256 + 8 pad) -> 528 bytes

struct Smem {
    __align__(16) __nv_bfloat16 Ah[TM][APITCH];   // 66 KB
    __align__(16) __nv_bfloat16 Al[TM][APITCH];   // 66 KB
    float w1[SD][D];                              // 14 KB
    float stats[TM][16];                          // 8 KB
    float b1[D];
    float b2[D];
};

__global__ void __launch_bounds__(THREADS, 1)
tte_mma_kernel(const int* __restrict__ y,
               const float* __restrict__ g_w1,
               const float* __restrict__ g_b1,
               const float* __restrict__ g_b2,
               float* __restrict__ out)
{
    extern __shared__ char smem_raw[];
    Smem& sm = *reinterpret_cast<Smem*>(smem_raw);

    const int tid  = threadIdx.x;
    const int lane = tid & 31;
    const int wid  = tid >> 5;          // 0..15
    const int task0 = blockIdx.x * TM;

    // ---- load w1/b1/b2 ----
    {
        float* w1f = &sm.w1[0][0];
        for (int i = tid; i < SD * D; i += THREADS) w1f[i] = g_w1[i];
        if (tid < D) { sm.b1[tid] = g_b1[tid]; sm.b2[tid] = g_b2[tid]; }
    }

    // ---- Phase 1: per-task histogram stats (warp per task, 8 tasks/warp) ----
#pragma unroll
    for (int it = 0; it < TM / 16; ++it) {
        const int tt = wid * (TM / 16) + it;
        const int4 yv = *reinterpret_cast<const int4*>(
            y + (size_t)(task0 + tt) * SLEN + lane * 4);
        int cnt[NCLS];
#pragma unroll
        for (int c = 0; c < NCLS; ++c) {
            int m = (yv.x == c) + (yv.y == c) + (yv.z == c) + (yv.w == c);
            cnt[c] = __reduce_add_sync(0xffffffffu, m);
        }
        if (lane == 0) {
            float ent = 0.0f, pmax = 0.0f;
            int   nnz = 0;
#pragma unroll
            for (int c = 0; c < NCLS; ++c) {
                float pc = (float)cnt[c] * (1.0f / (float)SLEN);
                sm.stats[tt][c] = pc;
                ent  -= pc * logf(pc + 1e-6f);
                nnz  += (cnt[c] > 0);
                pmax  = fmaxf(pmax, pc);
            }
            sm.stats[tt][10] = (float)nnz;
            sm.stats[tt][11] = ent;
            sm.stats[tt][12] = (float)SLEN;
            sm.stats[tt][13] = pmax;
        }
    }
    __syncthreads();

    // ---- Phase 2: h = gelu(stats @ w1 + b1) -> bf16 hi/lo smem images ----
    // 16 warps: warp owns rows [wid*8, wid*8+8), lane owns cols [lane*8, lane*8+8)
    {
        const int ty = wid;
        const int tx = lane;
        float acc[8][8];
#pragma unroll
        for (int i = 0; i < 8; ++i)
#pragma unroll
            for (int j = 0; j < 8; ++j) acc[i][j] = sm.b1[tx * 8 + j];
#pragma unroll
        for (int k = 0; k < SD; ++k) {
            float a[8], b[8];
#pragma unroll
            for (int i = 0; i < 8; ++i) a[i] = sm.stats[ty * 8 + i][k];
#pragma unroll
            for (int j = 0; j < 8; ++j) b[j] = sm.w1[k][tx * 8 + j];
#pragma unroll
            for (int i = 0; i < 8; ++i)
#pragma unroll
                for (int j = 0; j < 8; ++j) acc[i][j] = fmaf(a[i], b[j], acc[i][j]);
        }
#pragma unroll
        for (int i = 0; i < 8; ++i) {
            const int m = ty * 8 + i;
            uint32_t hi[4], lo[4];
#pragma unroll
            for (int q = 0; q < 4; ++q) {
                float x0 = acc[i][2 * q], x1 = acc[i][2 * q + 1];
                float g0 = 0.5f * x0 * (1.0f + erff(x0 * 0.70710678118654752f));
                float g1 = 0.5f * x1 * (1.0f + erff(x1 * 0.70710678118654752f));
                __nv_bfloat16 h0 = __float2bfloat16(g0);
                __nv_bfloat16 h1 = __float2bfloat16(g1);
                hi[q] = pack_bf16(__bfloat162float(h0), __bfloat162float(h1));
                lo[q] = pack_bf16(g0 - __bfloat162float(h0), g1 - __bfloat162float(h1));
            }
            *reinterpret_cast<uint4*>(&sm.Ah[m][tx * 8]) = make_uint4(hi[0], hi[1], hi[2], hi[3]);
            *reinterpret_cast<uint4*>(&sm.Al[m][tx * 8]) = make_uint4(lo[0], lo[1], lo[2], lo[3]);
        }
    }
    __syncthreads();

    // ---- Phase 3: out = h @ w2 + b2, interleaved 3-term (R9 structure, no B prefetch) ----
    // 16 warps: hw = wid>>3 -> rows [hw*64, hw*64+64); cg = wid&7 -> cols [cg*32, cg*32+32)
    const int hw = wid >> 3;
    const int cg = wid & 7;

    // verified lane->address map: a-regs [r0-7,k0-7],[r8-15,k0-7],[r0-7,k8-15],[r8-15,k8-15]
    const int arow_l = (lane & 7) + ((lane >> 3) & 1) * 8;
    const int kofs_l = (lane >> 4) * 16;

    float acc[4][4][4];
#pragma unroll
    for (int mt = 0; mt < 4; ++mt)
#pragma unroll
        for (int nt = 0; nt < 4; ++nt)
#pragma unroll
            for (int q = 0; q < 4; ++q) acc[mt][nt][q] = 0.0f;

    const uint32_t mstride = 16u * (APITCH * 2);
    uint32_t adrH = s2u(&sm.Ah[0][0]) + (uint32_t)((hw * 64 + arow_l) * (APITCH * 2) + kofs_l);
    uint32_t adrL = s2u(&sm.Al[0][0]) + (uint32_t)((hw * 64 + arow_l) * (APITCH * 2) + kofs_l);

    const uint4* __restrict__ bptrH = reinterpret_cast<const uint4*>(g_w2fH) + (cg * 32 + lane) * 2;
    const uint4* __restrict__ bptrL = reinterpret_cast<const uint4*>(g_w2fL) + (cg * 32 + lane) * 2;

#pragma unroll
    for (int kc = 0; kc < 16; ++kc) {
        // direct B loads for this kc (no register pipeline -> no spills)
        const uint4 h0 = bptrH[0], h1 = bptrH[1];
        const uint4 l0 = bptrL[0], l1 = bptrL[1];
        bptrH += BSTRIDE_U4; bptrL += BSTRIDE_U4;

        uint32_t ah[4][4], al[4][4];
#pragma unroll
        for (int mt = 0; mt < 4; ++mt) {
            ldsm4(ah[mt], adrH + mt * mstride);
            ldsm4(al[mt], adrL + mt * mstride);
        }
        adrH += 32;
        adrL += 32;

        const uint32_t bh[4][2] = { {h0.x, h0.y}, {h0.z, h0.w}, {h1.x, h1.y}, {h1.z, h1.w} };
        const uint32_t bl[4][2] = { {l0.x, l0.y}, {l0.z, l0.w}, {l1.x, l1.y}, {l1.z, l1.w} };

#pragma unroll
        for (int mt = 0; mt < 4; ++mt)
#pragma unroll
            for (int nt = 0; nt < 4; ++nt) {
                mma16816(acc[mt][nt], ah[mt], bh[nt][0], bh[nt][1]);
                mma16816(acc[mt][nt], ah[mt], bl[nt][0], bl[nt][1]);
                mma16816(acc[mt][nt], al[mt], bh[nt][0], bh[nt][1]);
            }
    }

    // ---- Epilogue: + b2, streaming store ----
    const int colb = cg * 32;
    const int r_in = lane >> 2;
    const int c_in = (lane & 3) * 2;
#pragma unroll
    for (int nt = 0; nt < 4; ++nt) {
        const int col = colb + nt * 8 + c_in;
        const float bb0 = sm.b2[col], bb1 = sm.b2[col + 1];
#pragma unroll
        for (int mt = 0; mt < 4; ++mt) {
            const size_t r0 = (size_t)(task0 + hw * 64 + mt * 16 + r_in);
            asm volatile("st.global.cs.v2.f32 [%0], {%1,%2};"
                         :: "l"(out + r0 * D + col),
                            "f"(acc[mt][nt][0] + bb0), "f"(acc[mt][nt][1] + bb1) : "memory");
            asm volatile("st.global.cs.v2.f32 [%0], {%1,%2};"
                         :: "l"(out + (r0 + 8) * D + col),
                            "f"(acc[mt][nt][2] + bb0), "f"(acc[mt][nt][3] + bb1) : "memory");
        }
    }
}

extern "C" void kernel_launch(void* const* d_in, const int* in_sizes, int n_in,
                              void* d_out, int out_size)
{
    (void)in_sizes; (void)n_in; (void)out_size;
    const int*   y  = (const int*)  d_in[0];
    const float* w1 = (const float*)d_in[1];
    const float* b1 = (const float*)d_in[2];
    const float* w2 = (const float*)d_in[3];
    const float* b2 = (const float*)d_in[4];
    float* out = (float*)d_out;

    prep_w2_kernel<<<64, 256>>>(w2);

    const int smem = (int)sizeof(Smem);
    cudaFuncSetAttribute(tte_mma_kernel,
                         cudaFuncAttributeMaxDynamicSharedMemorySize, smem);
    tte_mma_kernel<<<BATCH / TM, THREADS, smem>>>(y, w1, b1, b2, out);
}